// round 4
// baseline (speedup 1.0000x reference)
#include <cuda_runtime.h>
#include <cstdint>

// OmniAttention flash-forward, tf32 mma.sync. Q_TILE=128/CTA (32 q-rows/warp),
// KV_TILE=64 single-buffered, 3 CTAs/SM. Sequential row-tiles, smem-resident Q,
// shuffle-based P transpose (no P smem), exp2-domain softmax, exact tile skipping.

#define STRIDE 68  // padded smem row stride (words) for sK / sQ

__device__ __forceinline__ uint32_t f2tf(float x) {
    uint32_t r;
    asm("cvt.rna.tf32.f32 %0, %1;" : "=r"(r) : "f"(x));
    return r;
}
__device__ __forceinline__ float ex2f(float x) {
    float y;
    asm("ex2.approx.f32 %0, %1;" : "=f"(y) : "f"(x));
    return y;
}
__device__ __forceinline__ void cpa16(void* dst, const void* src) {
    uint32_t d = (uint32_t)__cvta_generic_to_shared(dst);
    asm volatile("cp.async.cg.shared.global [%0], [%1], 16;" :: "r"(d), "l"(src));
}
__device__ __forceinline__ void cpa4(void* dst, const void* src) {
    uint32_t d = (uint32_t)__cvta_generic_to_shared(dst);
    asm volatile("cp.async.ca.shared.global [%0], [%1], 4;" :: "r"(d), "l"(src));
}
__device__ __forceinline__ void mma8(float* c, const uint32_t* a, uint32_t b0, uint32_t b1) {
    asm volatile(
        "mma.sync.aligned.m16n8k8.row.col.f32.tf32.tf32.f32 "
        "{%0,%1,%2,%3}, {%4,%5,%6,%7}, {%8,%9}, {%0,%1,%2,%3};\n"
        : "+f"(c[0]), "+f"(c[1]), "+f"(c[2]), "+f"(c[3])
        : "r"(a[0]), "r"(a[1]), "r"(a[2]), "r"(a[3]), "r"(b0), "r"(b1));
}

__global__ void __launch_bounds__(128, 3)
omni_attn_kernel(const float* __restrict__ gq, const float* __restrict__ gk,
                 const float* __restrict__ gv,
                 const int* __restrict__ gpad, const int* __restrict__ gfs,
                 const int* __restrict__ gfe,
                 const int* __restrict__ p_bt2i, const int* __restrict__ p_blm,
                 float* __restrict__ gout, int H, int S)
{
    extern __shared__ float smem[];
    float* sK = smem;                  // 64 x STRIDE (padded)
    float* sV = sK + 64 * STRIDE;      // 64 x 64 (xor swizzled)
    float* sQ = sV + 64 * 64;          // 128 x STRIDE (persistent, prescaled tf32 Q)
    int*   sPad = (int*)(sQ + 128 * STRIDE);  // 64
    int*   sRed = sPad + 64;                  // 8

    const int tid  = threadIdx.x;
    const int warp = tid >> 5;
    const int lane = tid & 31;
    const int g = lane >> 2;
    const int t = lane & 3;

    const int q0 = blockIdx.x * 128;
    const int bh = blockIdx.y;
    const int b  = bh / H;

    const int bt2i = p_bt2i[0];
    const int blm  = p_blm[0];
    const int mode = (b < bt2i) ? 0 : ((b < bt2i + blm) ? 1 : 2);

    const size_t base = (size_t)bh * S * 64;

    // ---- stage Q tile (128x64), fold scale*log2e, tf32-round ----
    {
        const float qs = 0.125f * 1.4426950408889634f;
        const float4* src = (const float4*)(gq + base + (size_t)q0 * 64);
        #pragma unroll
        for (int i = tid; i < 2048; i += 128) {
            float4 x = src[i];
            float4 y;
            y.x = __uint_as_float(f2tf(x.x * qs));
            y.y = __uint_as_float(f2tf(x.y * qs));
            y.z = __uint_as_float(f2tf(x.z * qs));
            y.w = __uint_as_float(f2tf(x.w * qs));
            *(float4*)(sQ + (i >> 4) * STRIDE + ((i & 15) << 2)) = y;
        }
    }

    int qr[2][2];
    int fs[2][2] = {{0,0},{0,0}}, fe[2][2] = {{0,0},{0,0}};
    #pragma unroll
    for (int rt = 0; rt < 2; rt++) {
        qr[rt][0] = q0 + warp * 32 + rt * 16 + g;
        qr[rt][1] = qr[rt][0] + 8;
        if (mode == 0) {
            fs[rt][0] = gfs[qr[rt][0]]; fe[rt][0] = gfe[qr[rt][0]];
            fs[rt][1] = gfs[qr[rt][1]]; fe[rt][1] = gfe[qr[rt][1]];
        }
    }
    const int wmin = q0 + warp * 32;
    const int pe = (mode == 0) ? gpad[(size_t)b * S] : 0;

    // ---- data-driven kv range for this CTA ----
    int kv_end, kv_beg = 0;
    if (mode == 1) {
        kv_end = q0 + 128;
    } else if (mode == 2) {
        kv_end = q0 + 128;
        const int mmu_end = ((576 + 3) / 64 + 1) * 64;
        if (kv_end < mmu_end) kv_end = mmu_end;
    } else {
        int need = 0, strt = S;
        #pragma unroll
        for (int rt = 0; rt < 2; rt++)
            #pragma unroll
            for (int h = 0; h < 2; h++) {
                const int qq = qr[rt][h];
                int nd = qq + 1;
                if (fe[rt][h] > nd) nd = fe[rt][h];
                if (qq == pe) nd = S;                    // empty row: count all kv
                if (nd > need) need = nd;
                int st = (qq == pe) ? 0 : ((qq < pe) ? qq : pe);
                if (st < strt) strt = st;
            }
        need = __reduce_max_sync(0xffffffffu, need);
        strt = __reduce_min_sync(0xffffffffu, strt);
        if (lane == 0) { sRed[warp] = need; sRed[4 + warp] = strt; }
        __syncthreads();
        int mx = sRed[0], mn = sRed[4];
        #pragma unroll
        for (int w = 1; w < 4; w++) {
            if (sRed[w] > mx) mx = sRed[w];
            if (sRed[4 + w] < mn) mn = sRed[4 + w];
        }
        kv_end = (mx + 63) & ~63;
        kv_beg = mn & ~63;
    }
    if (kv_end > S) kv_end = S;

    float o[2][8][4];
    #pragma unroll
    for (int rt = 0; rt < 2; rt++)
        #pragma unroll
        for (int n = 0; n < 8; n++)
            o[rt][n][0] = o[rt][n][1] = o[rt][n][2] = o[rt][n][3] = 0.f;
    float m[2][2] = {{-1e30f,-1e30f},{-1e30f,-1e30f}};
    float l[2][2] = {{0.f,0.f},{0.f,0.f}};

    const int it0 = kv_beg >> 6, itN = kv_end >> 6;

    for (int it = it0; it < itN; it++) {
        const int kv0 = it << 6;

        __syncthreads();    // previous tile's reads of sK/sV complete
        {
            const float4* srcK = (const float4*)(gk + base + (size_t)kv0 * 64);
            const float4* srcV = (const float4*)(gv + base + (size_t)kv0 * 64);
            #pragma unroll
            for (int j = 0; j < 8; j++) {
                const int i = tid + j * 128;
                const int row = i >> 4, c4 = (i & 15) << 2;
                cpa16(sK + row * STRIDE + c4, srcK + i);
                cpa16(sV + row * 64 + (c4 ^ ((row & 7) << 3)), srcV + i);
            }
            if (mode == 0 && tid < 64) cpa4(sPad + tid, gpad + (size_t)b * S + kv0 + tid);
            asm volatile("cp.async.commit_group;");
            asm volatile("cp.async.wait_group 0;");
        }
        __syncthreads();    // tile visible

        // ---- per-warp fully-masked-tile skip ----
        bool wskip;
        if (mode == 1) {
            wskip = kv0 > wmin + 31;
        } else if (mode == 2) {
            wskip = (kv0 > wmin + 31) && (kv0 > 579);
        } else {
            bool th_skip = true;
            #pragma unroll
            for (int rt = 0; rt < 2; rt++)
                #pragma unroll
                for (int h = 0; h < 2; h++) {
                    const int r = qr[rt][h];
                    const bool no_caus = (kv0 > r) || (kv0 + 63 < pe);
                    const bool no_full = (kv0 >= fe[rt][h]) || (kv0 + 63 < fs[rt][h]);
                    const bool no_diag = (r < kv0) || (r > kv0 + 63);
                    th_skip = th_skip && no_caus && no_full && no_diag && (r != pe);
                }
            wskip = __all_sync(0xffffffffu, th_skip);
        }
        if (wskip) continue;

        // ---- unmasked-tile fast path test ----
        bool nomask;
        if (mode == 1) {
            nomask = (kv0 + 63 <= wmin);
        } else if (mode == 2) {
            nomask = (kv0 + 63 <= 579) || (kv0 + 63 <= wmin);
        } else {
            bool th_nm = true;
            #pragma unroll
            for (int rt = 0; rt < 2; rt++)
                #pragma unroll
                for (int h = 0; h < 2; h++) {
                    const int r = qr[rt][h];
                    const bool full_cov = (fs[rt][h] <= kv0) && (kv0 + 63 < fe[rt][h]) &&
                                          (r < kv0 || r > kv0 + 63);
                    const bool caus_cov = (kv0 >= pe) && (kv0 + 63 < r);
                    th_nm = th_nm && (full_cov || caus_cov);
                }
            nomask = __all_sync(0xffffffffu, th_nm);
        }

        // ---- process the two 16-row tiles sequentially (low register pressure) ----
        #pragma unroll
        for (int rt = 0; rt < 2; rt++) {
            // Q fragments for this row-tile from smem
            uint32_t qa[8][4];
            {
                const int r0s = (warp * 32 + rt * 16 + g) * STRIDE;
                #pragma unroll
                for (int kt = 0; kt < 8; kt++) {
                    qa[kt][0] = __float_as_uint(sQ[r0s              + kt * 8 + t]);
                    qa[kt][1] = __float_as_uint(sQ[r0s + 8 * STRIDE + kt * 8 + t]);
                    qa[kt][2] = __float_as_uint(sQ[r0s              + kt * 8 + t + 4]);
                    qa[kt][3] = __float_as_uint(sQ[r0s + 8 * STRIDE + kt * 8 + t + 4]);
                }
            }

            // S = Q @ K^T (scores already scaled, log2 domain)
            float c[8][4];
            #pragma unroll
            for (int n = 0; n < 8; n++) {
                c[n][0] = c[n][1] = c[n][2] = c[n][3] = 0.f;
                #pragma unroll
                for (int kt = 0; kt < 8; kt++) {
                    const uint32_t b0 = __float_as_uint(sK[(n * 8 + g) * STRIDE + kt * 8 + t]);
                    const uint32_t b1 = __float_as_uint(sK[(n * 8 + g) * STRIDE + kt * 8 + t + 4]);
                    mma8(c[n], qa[kt], b0, b1);
                }
            }

            const int r0 = qr[rt][0], r1 = qr[rt][1];
            if (!nomask) {
                #pragma unroll
                for (int n = 0; n < 8; n++) {
                    const int col0 = kv0 + n * 8 + 2 * t;
                    const int col1 = col0 + 1;
                    bool m00, m01, m10, m11;
                    if (mode == 1) {
                        m00 = r0 >= col0; m01 = r0 >= col1;
                        m10 = r1 >= col0; m11 = r1 >= col1;
                    } else if (mode == 2) {
                        const bool c0c = col0 <= 579, c1c = col1 <= 579;
                        m00 = (r0 >= col0) || c0c; m01 = (r0 >= col1) || c1c;
                        m10 = (r1 >= col0) || c0c; m11 = (r1 >= col1) || c1c;
                    } else {
                        const bool pad0 = col0 < sPad[n * 8 + 2 * t];
                        const bool pad1 = col1 < sPad[n * 8 + 2 * t + 1];
                        const bool f00 = (col0 < fe[rt][0]) && (col0 >= fs[rt][0]);
                        const bool f01 = (col1 < fe[rt][0]) && (col1 >= fs[rt][0]);
                        const bool f10 = (col0 < fe[rt][1]) && (col0 >= fs[rt][1]);
                        const bool f11 = (col1 < fe[rt][1]) && (col1 >= fs[rt][1]);
                        m00 = (r0 == col0) != ((!pad0 && (r0 >= col0)) || f00);
                        m01 = (r0 == col1) != ((!pad1 && (r0 >= col1)) || f01);
                        m10 = (r1 == col0) != ((!pad0 && (r1 >= col0)) || f10);
                        m11 = (r1 == col1) != ((!pad1 && (r1 >= col1)) || f11);
                    }
                    if (!m00) c[n][0] = -1e30f;
                    if (!m01) c[n][1] = -1e30f;
                    if (!m10) c[n][2] = -1e30f;
                    if (!m11) c[n][3] = -1e30f;
                }
            }

            // ---- online softmax in exp2 domain (quad owns two rows) ----
            float tm0 = -1e30f, tm1 = -1e30f;
            #pragma unroll
            for (int n = 0; n < 8; n++) {
                tm0 = fmaxf(tm0, fmaxf(c[n][0], c[n][1]));
                tm1 = fmaxf(tm1, fmaxf(c[n][2], c[n][3]));
            }
            tm0 = fmaxf(tm0, __shfl_xor_sync(0xffffffffu, tm0, 1));
            tm0 = fmaxf(tm0, __shfl_xor_sync(0xffffffffu, tm0, 2));
            tm1 = fmaxf(tm1, __shfl_xor_sync(0xffffffffu, tm1, 1));
            tm1 = fmaxf(tm1, __shfl_xor_sync(0xffffffffu, tm1, 2));
            const float mn0 = fmaxf(m[rt][0], tm0), mn1 = fmaxf(m[rt][1], tm1);
            const float al0 = ex2f(m[rt][0] - mn0), al1 = ex2f(m[rt][1] - mn1);
            float s0 = 0.f, s1 = 0.f;
            #pragma unroll
            for (int n = 0; n < 8; n++) {
                c[n][0] = ex2f(c[n][0] - mn0);
                c[n][1] = ex2f(c[n][1] - mn0);
                c[n][2] = ex2f(c[n][2] - mn1);
                c[n][3] = ex2f(c[n][3] - mn1);
                s0 += c[n][0] + c[n][1];
                s1 += c[n][2] + c[n][3];
            }
            s0 += __shfl_xor_sync(0xffffffffu, s0, 1);
            s0 += __shfl_xor_sync(0xffffffffu, s0, 2);
            s1 += __shfl_xor_sync(0xffffffffu, s1, 1);
            s1 += __shfl_xor_sync(0xffffffffu, s1, 2);
            l[rt][0] = l[rt][0] * al0 + s0;
            l[rt][1] = l[rt][1] * al1 + s1;
            m[rt][0] = mn0; m[rt][1] = mn1;
            #pragma unroll
            for (int n = 0; n < 8; n++) {
                o[rt][n][0] *= al0; o[rt][n][1] *= al0;
                o[rt][n][2] *= al1; o[rt][n][3] *= al1;
            }

            // ---- O += P @ V with in-register quad-shuffle transpose of P ----
            const int src0 = (lane & ~3) | (t >> 1);
            const bool odd = (t & 1);
            #pragma unroll
            for (int kt = 0; kt < 8; kt++) {
                // C-frag c[kt] -> A-frag (rows g,g+8; cols 8kt+t, 8kt+t+4)
                const float x0 = __shfl_sync(0xffffffffu, c[kt][0], src0);
                const float x1 = __shfl_sync(0xffffffffu, c[kt][1], src0);
                const float y0 = __shfl_sync(0xffffffffu, c[kt][2], src0);
                const float y1 = __shfl_sync(0xffffffffu, c[kt][3], src0);
                const float z0 = __shfl_sync(0xffffffffu, c[kt][0], src0 + 2);
                const float z1 = __shfl_sync(0xffffffffu, c[kt][1], src0 + 2);
                const float w0 = __shfl_sync(0xffffffffu, c[kt][2], src0 + 2);
                const float w1 = __shfl_sync(0xffffffffu, c[kt][3], src0 + 2);
                uint32_t pa[4];
                pa[0] = __float_as_uint(odd ? x1 : x0);   // P[g   ][8kt+t]
                pa[1] = __float_as_uint(odd ? y1 : y0);   // P[g+8 ][8kt+t]
                pa[2] = __float_as_uint(odd ? z1 : z0);   // P[g   ][8kt+t+4]
                pa[3] = __float_as_uint(odd ? w1 : w0);   // P[g+8 ][8kt+t+4]

                const int vr0 = (8 * kt + t) * 64 + g;
                const int vr1 = (8 * kt + t + 4) * 64 + g;
                #pragma unroll
                for (int n = 0; n < 8; n++) {
                    const uint32_t b0 = __float_as_uint(sV[vr0 + 8 * (n ^ t)]);
                    const uint32_t b1 = __float_as_uint(sV[vr1 + 8 * ((n ^ t) ^ 4)]);
                    mma8(o[rt][n], pa, b0, b1);
                }
            }
        }
    }

    // ---- epilogue ----
    #pragma unroll
    for (int rt = 0; rt < 2; rt++) {
        const float inv0 = 1.f / l[rt][0], inv1 = 1.f / l[rt][1];
        float* orow0 = gout + base + (size_t)qr[rt][0] * 64;
        float* orow1 = gout + base + (size_t)qr[rt][1] * 64;
        #pragma unroll
        for (int n = 0; n < 8; n++) {
            float2 w0 = make_float2(o[rt][n][0] * inv0, o[rt][n][1] * inv0);
            float2 w1 = make_float2(o[rt][n][2] * inv1, o[rt][n][3] * inv1);
            *(float2*)(orow0 + n * 8 + 2 * t) = w0;
            *(float2*)(orow1 + n * 8 + 2 * t) = w1;
        }
    }
}

extern "C" void kernel_launch(void* const* d_in, const int* in_sizes, int n_in,
                              void* d_out, int out_size)
{
    const float* q   = (const float*)d_in[0];
    const float* k   = (const float*)d_in[1];
    const float* v   = (const float*)d_in[2];
    const int* pad   = (const int*)d_in[3];
    const int* fs    = (const int*)d_in[4];
    const int* fe    = (const int*)d_in[5];
    const int* bt2i  = (const int*)d_in[6];
    const int* blm   = (const int*)d_in[7];
    float* out = (float*)d_out;

    const int S = in_sizes[4];
    const int B = in_sizes[3] / S;
    const int H = (int)((long long)in_sizes[0] / ((long long)B * S * 64));

    const size_t smem = (size_t)(64 * STRIDE + 64 * 64 + 128 * STRIDE) * sizeof(float)
                      + 72 * sizeof(int);
    cudaFuncSetAttribute(omni_attn_kernel,
                         cudaFuncAttributeMaxDynamicSharedMemorySize, (int)smem);

    dim3 grid(S / 128, B * H);
    omni_attn_kernel<<<grid, 128, smem>>>(q, k, v, pad, fs, fe, bt2i, blm, out, H, S);
}

// round 5
// speedup vs baseline: 1.4843x; 1.4843x over previous
#include <cuda_runtime.h>
#include <cstdint>

// OmniAttention flash-forward, tf32 mma.sync.
// Q_TILE=128/CTA (32 q-rows/warp, Q fragments register-resident),
// KV_TILE=32 double-buffered cp.async, 3 CTAs/SM, shared B-frags across the
// two 16-row tiles, shuffle-based P transpose, exp2-domain softmax,
// pad-aware tile skipping + CTA-level kv range.

#define STRIDE 68  // padded smem row stride (words) for K / Q staging

__device__ __forceinline__ uint32_t f2tf(float x) {
    uint32_t r;
    asm("cvt.rna.tf32.f32 %0, %1;" : "=r"(r) : "f"(x));
    return r;
}
__device__ __forceinline__ float ex2f(float x) {
    float y;
    asm("ex2.approx.f32 %0, %1;" : "=f"(y) : "f"(x));
    return y;
}
__device__ __forceinline__ void cpa16(void* dst, const void* src) {
    uint32_t d = (uint32_t)__cvta_generic_to_shared(dst);
    asm volatile("cp.async.cg.shared.global [%0], [%1], 16;" :: "r"(d), "l"(src));
}
__device__ __forceinline__ void cpa4(void* dst, const void* src) {
    uint32_t d = (uint32_t)__cvta_generic_to_shared(dst);
    asm volatile("cp.async.ca.shared.global [%0], [%1], 4;" :: "r"(d), "l"(src));
}
__device__ __forceinline__ void mma8(float* c, const uint32_t* a, uint32_t b0, uint32_t b1) {
    asm volatile(
        "mma.sync.aligned.m16n8k8.row.col.f32.tf32.tf32.f32 "
        "{%0,%1,%2,%3}, {%4,%5,%6,%7}, {%8,%9}, {%0,%1,%2,%3};\n"
        : "+f"(c[0]), "+f"(c[1]), "+f"(c[2]), "+f"(c[3])
        : "r"(a[0]), "r"(a[1]), "r"(a[2]), "r"(a[3]), "r"(b0), "r"(b1));
}

// Load one 32x64 K/V tile pair into the given smem stage (K padded, V swizzled).
__device__ __forceinline__ void preload_kv(float* dK, float* dV,
                                           const float* gk, const float* gv,
                                           size_t base, int kv0, int tid) {
    const float4* srcK = (const float4*)(gk + base + (size_t)kv0 * 64);
    const float4* srcV = (const float4*)(gv + base + (size_t)kv0 * 64);
    #pragma unroll
    for (int j = 0; j < 4; j++) {
        const int i = tid + j * 128;
        const int row = i >> 4, c4 = (i & 15) << 2;
        cpa16(dK + row * STRIDE + c4, srcK + i);
        cpa16(dV + row * 64 + (c4 ^ ((row & 7) << 3)), srcV + i);
    }
}

__global__ void __launch_bounds__(128, 3)
omni_attn_kernel(const float* __restrict__ gq, const float* __restrict__ gk,
                 const float* __restrict__ gv,
                 const int* __restrict__ gpad, const int* __restrict__ gfs,
                 const int* __restrict__ gfe,
                 const int* __restrict__ p_bt2i, const int* __restrict__ p_blm,
                 float* __restrict__ gout, int H, int S)
{
    extern __shared__ float smem[];
    // KV region (after Q staging phase):
    float* sK   = smem;                         // 2 stages x 32 x STRIDE
    float* sV   = smem + 2 * 32 * STRIDE;       // 2 stages x 32 x 64 (xor swizzled)
    int*   sPad = (int*)(smem + 2 * 32 * STRIDE + 2 * 32 * 64);  // 2 stages x 32
    // Q staging overlay: smem[0 .. 128*STRIDE) — used only before the KV loop.
    float* sQ   = smem;
    int*   sRed = (int*)(smem + 128 * STRIDE);  // 8 (outside Q overlay)

    const int tid  = threadIdx.x;
    const int warp = tid >> 5;
    const int lane = tid & 31;
    const int g = lane >> 2;
    const int t = lane & 3;

    const int q0 = blockIdx.x * 128;
    const int bh = blockIdx.y;
    const int b  = bh / H;

    const int bt2i = p_bt2i[0];
    const int blm  = p_blm[0];
    const int mode = (b < bt2i) ? 0 : ((b < bt2i + blm) ? 1 : 2);

    const size_t base = (size_t)bh * S * 64;

    // ---- stage Q tile (128x64), fold scale*log2e, tf32-round ----
    {
        const float qs = 0.125f * 1.4426950408889634f;
        const float4* src = (const float4*)(gq + base + (size_t)q0 * 64);
        #pragma unroll
        for (int i = tid; i < 2048; i += 128) {
            float4 x = src[i];
            float4 y;
            y.x = __uint_as_float(f2tf(x.x * qs));
            y.y = __uint_as_float(f2tf(x.y * qs));
            y.z = __uint_as_float(f2tf(x.z * qs));
            y.w = __uint_as_float(f2tf(x.w * qs));
            *(float4*)(sQ + (i >> 4) * STRIDE + ((i & 15) << 2)) = y;
        }
    }

    int qr[2][2];
    int fs[2][2] = {{0,0},{0,0}}, fe[2][2] = {{0,0},{0,0}};
    #pragma unroll
    for (int rt = 0; rt < 2; rt++) {
        qr[rt][0] = q0 + warp * 32 + rt * 16 + g;
        qr[rt][1] = qr[rt][0] + 8;
        if (mode == 0) {
            fs[rt][0] = gfs[qr[rt][0]]; fe[rt][0] = gfe[qr[rt][0]];
            fs[rt][1] = gfs[qr[rt][1]]; fe[rt][1] = gfe[qr[rt][1]];
        }
    }
    const int wmin = q0 + warp * 32;
    const int pe = (mode == 0) ? gpad[(size_t)b * S] : 0;

    __syncthreads();   // Q staged

    // ---- Q fragments register-resident for the whole kernel ----
    uint32_t qa[2][8][4];
    #pragma unroll
    for (int rt = 0; rt < 2; rt++) {
        const int r0s = (warp * 32 + rt * 16 + g) * STRIDE;
        #pragma unroll
        for (int kt = 0; kt < 8; kt++) {
            qa[rt][kt][0] = __float_as_uint(sQ[r0s              + kt * 8 + t]);
            qa[rt][kt][1] = __float_as_uint(sQ[r0s + 8 * STRIDE + kt * 8 + t]);
            qa[rt][kt][2] = __float_as_uint(sQ[r0s              + kt * 8 + t + 4]);
            qa[rt][kt][3] = __float_as_uint(sQ[r0s + 8 * STRIDE + kt * 8 + t + 4]);
        }
    }

    // ---- data-driven kv range for this CTA ----
    int kv_end, kv_beg = 0;
    if (mode == 1) {
        kv_end = q0 + 128;
    } else if (mode == 2) {
        kv_end = q0 + 128;
        if (kv_end < 580) kv_end = 580;    // kv <= 579 always visible
    } else {
        int need = 0, strt = S;
        #pragma unroll
        for (int rt = 0; rt < 2; rt++)
            #pragma unroll
            for (int h = 0; h < 2; h++) {
                const int qq = qr[rt][h];
                int nd = qq + 1;
                if (fe[rt][h] > nd) nd = fe[rt][h];
                if (qq == pe) nd = S;                    // empty row: count all kv
                if (nd > need) need = nd;
                int st = (qq == pe) ? 0 : ((qq < pe) ? qq : pe);
                if (st < strt) strt = st;
            }
        need = __reduce_max_sync(0xffffffffu, need);
        strt = __reduce_min_sync(0xffffffffu, strt);
        if (lane == 0) { sRed[warp] = need; sRed[4 + warp] = strt; }
        __syncthreads();   // also orders qa reads before KV overwrites sQ region
        int mx = sRed[0], mn = sRed[4];
        #pragma unroll
        for (int w = 1; w < 4; w++) {
            if (sRed[w] > mx) mx = sRed[w];
            if (sRed[4 + w] < mn) mn = sRed[4 + w];
        }
        kv_end = mx;
        kv_beg = mn & ~31;
    }
    if (mode != 0) __syncthreads();   // qa reads done before KV overwrite
    if (kv_end > S) kv_end = S;
    const int it0 = kv_beg >> 5;
    const int itN = (kv_end + 31) >> 5;

    float o[2][8][4];
    #pragma unroll
    for (int rt = 0; rt < 2; rt++)
        #pragma unroll
        for (int n = 0; n < 8; n++)
            o[rt][n][0] = o[rt][n][1] = o[rt][n][2] = o[rt][n][3] = 0.f;
    float m[2][2] = {{-1e30f,-1e30f},{-1e30f,-1e30f}};
    float l[2][2] = {{0.f,0.f},{0.f,0.f}};

    // ---- preload first tile ----
    {
        const int stg0 = it0 & 1;
        preload_kv(sK + stg0 * 32 * STRIDE, sV + stg0 * 32 * 64, gk, gv, base, it0 << 5, tid);
        if (mode == 0 && tid < 32) cpa4(sPad + stg0 * 32 + tid, gpad + (size_t)b * S + (it0 << 5) + tid);
        asm volatile("cp.async.commit_group;");
    }

    for (int it = it0; it < itN; it++) {
        const int kv0 = it << 5;
        const int stg = it & 1;
        const float* sKs = sK + stg * 32 * STRIDE;
        const float* sVs = sV + stg * 32 * 64;
        const int*   sPs = sPad + stg * 32;

        if (it + 1 < itN) {
            const int nstg = stg ^ 1;
            preload_kv(sK + nstg * 32 * STRIDE, sV + nstg * 32 * 64, gk, gv, base, kv0 + 32, tid);
            if (mode == 0 && tid < 32)
                cpa4(sPad + nstg * 32 + tid, gpad + (size_t)b * S + kv0 + 32 + tid);
            asm volatile("cp.async.commit_group;");
            asm volatile("cp.async.wait_group 1;");
        } else {
            asm volatile("cp.async.wait_group 0;");
        }
        __syncthreads();   // tile it visible to all

        // ---- per-warp fully-masked-tile skip ----
        bool wskip;
        if (mode == 1) {
            wskip = kv0 > wmin + 31;
        } else if (mode == 2) {
            wskip = (kv0 > wmin + 31) && (kv0 > 579);
        } else {
            bool th_skip = true;
            #pragma unroll
            for (int rt = 0; rt < 2; rt++)
                #pragma unroll
                for (int h = 0; h < 2; h++) {
                    const int r = qr[rt][h];
                    const bool no_caus = (kv0 > r) || (kv0 + 31 < pe);
                    const bool no_full = (kv0 >= fe[rt][h]) || (kv0 + 31 < fs[rt][h]);
                    const bool no_diag = (r < kv0) || (r > kv0 + 31);
                    th_skip = th_skip && no_caus && no_full && no_diag && (r != pe);
                }
            wskip = __all_sync(0xffffffffu, th_skip);
        }

        if (!wskip) {
            // ---- unmasked-tile fast path test ----
            bool nomask;
            if (mode == 1) {
                nomask = (kv0 + 31 <= wmin);
            } else if (mode == 2) {
                nomask = (kv0 + 31 <= 579) || (kv0 + 31 <= wmin);
            } else {
                bool th_nm = true;
                #pragma unroll
                for (int rt = 0; rt < 2; rt++)
                    #pragma unroll
                    for (int h = 0; h < 2; h++) {
                        const int r = qr[rt][h];
                        const bool full_cov = (fs[rt][h] <= kv0) && (kv0 + 31 < fe[rt][h]) &&
                                              (r < kv0 || r > kv0 + 31);
                        const bool caus_cov = (kv0 >= pe) && (kv0 + 31 < r);
                        th_nm = th_nm && (full_cov || caus_cov);
                    }
                nomask = __all_sync(0xffffffffu, th_nm);
            }

            // ---- S = Q @ K^T, both row-tiles share K B-frags ----
            float c[2][4][4];
            #pragma unroll
            for (int n = 0; n < 4; n++) {
                c[0][n][0] = c[0][n][1] = c[0][n][2] = c[0][n][3] = 0.f;
                c[1][n][0] = c[1][n][1] = c[1][n][2] = c[1][n][3] = 0.f;
                #pragma unroll
                for (int kt = 0; kt < 8; kt++) {
                    const uint32_t b0 = __float_as_uint(sKs[(n * 8 + g) * STRIDE + kt * 8 + t]);
                    const uint32_t b1 = __float_as_uint(sKs[(n * 8 + g) * STRIDE + kt * 8 + t + 4]);
                    mma8(c[0][n], qa[0][kt], b0, b1);
                    mma8(c[1][n], qa[1][kt], b0, b1);
                }
            }

            // ---- mask + online softmax per row-tile ----
            #pragma unroll
            for (int rt = 0; rt < 2; rt++) {
                const int r0 = qr[rt][0], r1 = qr[rt][1];
                if (!nomask) {
                    #pragma unroll
                    for (int n = 0; n < 4; n++) {
                        const int col0 = kv0 + n * 8 + 2 * t;
                        const int col1 = col0 + 1;
                        bool m00, m01, m10, m11;
                        if (mode == 1) {
                            m00 = r0 >= col0; m01 = r0 >= col1;
                            m10 = r1 >= col0; m11 = r1 >= col1;
                        } else if (mode == 2) {
                            const bool c0c = col0 <= 579, c1c = col1 <= 579;
                            m00 = (r0 >= col0) || c0c; m01 = (r0 >= col1) || c1c;
                            m10 = (r1 >= col0) || c0c; m11 = (r1 >= col1) || c1c;
                        } else {
                            const bool pad0 = col0 < sPs[n * 8 + 2 * t];
                            const bool pad1 = col1 < sPs[n * 8 + 2 * t + 1];
                            const bool f00 = (col0 < fe[rt][0]) && (col0 >= fs[rt][0]);
                            const bool f01 = (col1 < fe[rt][0]) && (col1 >= fs[rt][0]);
                            const bool f10 = (col0 < fe[rt][1]) && (col0 >= fs[rt][1]);
                            const bool f11 = (col1 < fe[rt][1]) && (col1 >= fs[rt][1]);
                            m00 = (r0 == col0) != ((!pad0 && (r0 >= col0)) || f00);
                            m01 = (r0 == col1) != ((!pad1 && (r0 >= col1)) || f01);
                            m10 = (r1 == col0) != ((!pad0 && (r1 >= col0)) || f10);
                            m11 = (r1 == col1) != ((!pad1 && (r1 >= col1)) || f11);
                        }
                        if (!m00) c[rt][n][0] = -1e30f;
                        if (!m01) c[rt][n][1] = -1e30f;
                        if (!m10) c[rt][n][2] = -1e30f;
                        if (!m11) c[rt][n][3] = -1e30f;
                    }
                }

                float tm0 = -1e30f, tm1 = -1e30f;
                #pragma unroll
                for (int n = 0; n < 4; n++) {
                    tm0 = fmaxf(tm0, fmaxf(c[rt][n][0], c[rt][n][1]));
                    tm1 = fmaxf(tm1, fmaxf(c[rt][n][2], c[rt][n][3]));
                }
                tm0 = fmaxf(tm0, __shfl_xor_sync(0xffffffffu, tm0, 1));
                tm0 = fmaxf(tm0, __shfl_xor_sync(0xffffffffu, tm0, 2));
                tm1 = fmaxf(tm1, __shfl_xor_sync(0xffffffffu, tm1, 1));
                tm1 = fmaxf(tm1, __shfl_xor_sync(0xffffffffu, tm1, 2));
                const float mn0 = fmaxf(m[rt][0], tm0), mn1 = fmaxf(m[rt][1], tm1);
                const float al0 = ex2f(m[rt][0] - mn0), al1 = ex2f(m[rt][1] - mn1);
                float s0 = 0.f, s1 = 0.f;
                #pragma unroll
                for (int n = 0; n < 4; n++) {
                    c[rt][n][0] = ex2f(c[rt][n][0] - mn0);
                    c[rt][n][1] = ex2f(c[rt][n][1] - mn0);
                    c[rt][n][2] = ex2f(c[rt][n][2] - mn1);
                    c[rt][n][3] = ex2f(c[rt][n][3] - mn1);
                    s0 += c[rt][n][0] + c[rt][n][1];
                    s1 += c[rt][n][2] + c[rt][n][3];
                }
                s0 += __shfl_xor_sync(0xffffffffu, s0, 1);
                s0 += __shfl_xor_sync(0xffffffffu, s0, 2);
                s1 += __shfl_xor_sync(0xffffffffu, s1, 1);
                s1 += __shfl_xor_sync(0xffffffffu, s1, 2);
                l[rt][0] = l[rt][0] * al0 + s0;
                l[rt][1] = l[rt][1] * al1 + s1;
                m[rt][0] = mn0; m[rt][1] = mn1;
                #pragma unroll
                for (int n = 0; n < 8; n++) {
                    o[rt][n][0] *= al0; o[rt][n][1] *= al0;
                    o[rt][n][2] *= al1; o[rt][n][3] *= al1;
                }
            }

            // ---- O += P @ V; shuffle-transpose P, V B-frags shared across row-tiles ----
            const int src0 = (lane & ~3) | (t >> 1);
            const bool odd = (t & 1);
            #pragma unroll
            for (int kt = 0; kt < 4; kt++) {
                uint32_t pa0[4], pa1[4];
                {
                    const float x0 = __shfl_sync(0xffffffffu, c[0][kt][0], src0);
                    const float x1 = __shfl_sync(0xffffffffu, c[0][kt][1], src0);
                    const float y0 = __shfl_sync(0xffffffffu, c[0][kt][2], src0);
                    const float y1 = __shfl_sync(0xffffffffu, c[0][kt][3], src0);
                    const float z0 = __shfl_sync(0xffffffffu, c[0][kt][0], src0 + 2);
                    const float z1 = __shfl_sync(0xffffffffu, c[0][kt][1], src0 + 2);
                    const float w0 = __shfl_sync(0xffffffffu, c[0][kt][2], src0 + 2);
                    const float w1 = __shfl_sync(0xffffffffu, c[0][kt][3], src0 + 2);
                    pa0[0] = __float_as_uint(odd ? x1 : x0);
                    pa0[1] = __float_as_uint(odd ? y1 : y0);
                    pa0[2] = __float_as_uint(odd ? z1 : z0);
                    pa0[3] = __float_as_uint(odd ? w1 : w0);
                }
                {
                    const float x0 = __shfl_sync(0xffffffffu, c[1][kt][0], src0);
                    const float x1 = __shfl_sync(0xffffffffu, c[1][kt][1], src0);
                    const float y0 = __shfl_sync(0xffffffffu, c[1][kt][2], src0);
                    const float y1 = __shfl_sync(0xffffffffu, c[1][kt][3], src0);
                    const float z0 = __shfl_sync(0xffffffffu, c[1][kt][0], src0 + 2);
                    const float z1 = __shfl_sync(0xffffffffu, c[1][kt][1], src0 + 2);
                    const float w0 = __shfl_sync(0xffffffffu, c[1][kt][2], src0 + 2);
                    const float w1 = __shfl_sync(0xffffffffu, c[1][kt][3], src0 + 2);
                    pa1[0] = __float_as_uint(odd ? x1 : x0);
                    pa1[1] = __float_as_uint(odd ? y1 : y0);
                    pa1[2] = __float_as_uint(odd ? z1 : z0);
                    pa1[3] = __float_as_uint(odd ? w1 : w0);
                }
                const int vr0 = (8 * kt + t) * 64 + g;
                const int vr1 = (8 * kt + t + 4) * 64 + g;
                #pragma unroll
                for (int n = 0; n < 8; n++) {
                    const uint32_t b0 = __float_as_uint(sVs[vr0 + 8 * (n ^ t)]);
                    const uint32_t b1 = __float_as_uint(sVs[vr1 + 8 * ((n ^ t) ^ 4)]);
                    mma8(o[0][n], pa0, b0, b1);
                    mma8(o[1][n], pa1, b0, b1);
                }
            }
        }

        __syncthreads();   // all reads of stage stg done before it+2 overwrites it
    }

    // ---- epilogue ----
    #pragma unroll
    for (int rt = 0; rt < 2; rt++) {
        const float inv0 = 1.f / l[rt][0], inv1 = 1.f / l[rt][1];
        float* orow0 = gout + base + (size_t)qr[rt][0] * 64;
        float* orow1 = gout + base + (size_t)qr[rt][1] * 64;
        #pragma unroll
        for (int n = 0; n < 8; n++) {
            float2 w0 = make_float2(o[rt][n][0] * inv0, o[rt][n][1] * inv0);
            float2 w1 = make_float2(o[rt][n][2] * inv1, o[rt][n][3] * inv1);
            *(float2*)(orow0 + n * 8 + 2 * t) = w0;
            *(float2*)(orow1 + n * 8 + 2 * t) = w1;
        }
    }
}

extern "C" void kernel_launch(void* const* d_in, const int* in_sizes, int n_in,
                              void* d_out, int out_size)
{
    const float* q   = (const float*)d_in[0];
    const float* k   = (const float*)d_in[1];
    const float* v   = (const float*)d_in[2];
    const int* pad   = (const int*)d_in[3];
    const int* fs    = (const int*)d_in[4];
    const int* fe    = (const int*)d_in[5];
    const int* bt2i  = (const int*)d_in[6];
    const int* blm   = (const int*)d_in[7];
    float* out = (float*)d_out;

    const int S = in_sizes[4];
    const int B = in_sizes[3] / S;
    const int H = (int)((long long)in_sizes[0] / ((long long)B * S * 64));

    // smem: Q staging overlay 128*STRIDE words, plus sRed (8 ints) after it.
    const size_t smem_bytes = (size_t)(128 * STRIDE + 8) * sizeof(float);
    cudaFuncSetAttribute(omni_attn_kernel,
                         cudaFuncAttributeMaxDynamicSharedMemorySize, (int)smem_bytes);

    dim3 grid(S / 128, B * H);
    omni_attn_kernel<<<grid, 128, smem_bytes>>>(q, k, v, pad, fs, fe, bt2i, blm, out, H, S);
}

// round 6
// speedup vs baseline: 1.8060x; 1.2167x over previous
#include <cuda_runtime.h>
#include <cstdint>

// OmniAttention flash-forward, tf32 mma.sync.
// 256 threads/CTA (8 warps), Q_TILE=128/CTA => 16 q-rows per warp (one MMA row-tile).
// KV_TILE=64 double-buffered cp.async, 2 CTAs/SM (16 warps/SM), shuffle-based
// P transpose, exp2-domain softmax, exact mask tile skipping.

#define STRIDE 68  // padded smem row stride (words) for K / Q

__device__ __forceinline__ uint32_t f2tf(float x) {
    uint32_t r;
    asm("cvt.rna.tf32.f32 %0, %1;" : "=r"(r) : "f"(x));
    return r;
}
__device__ __forceinline__ float ex2f(float x) {
    float y;
    asm("ex2.approx.f32 %0, %1;" : "=f"(y) : "f"(x));
    return y;
}
__device__ __forceinline__ void cpa16(void* dst, const void* src) {
    uint32_t d = (uint32_t)__cvta_generic_to_shared(dst);
    asm volatile("cp.async.cg.shared.global [%0], [%1], 16;" :: "r"(d), "l"(src));
}
__device__ __forceinline__ void cpa4(void* dst, const void* src) {
    uint32_t d = (uint32_t)__cvta_generic_to_shared(dst);
    asm volatile("cp.async.ca.shared.global [%0], [%1], 4;" :: "r"(d), "l"(src));
}
__device__ __forceinline__ void mma8(float* c, const uint32_t* a, uint32_t b0, uint32_t b1) {
    asm volatile(
        "mma.sync.aligned.m16n8k8.row.col.f32.tf32.tf32.f32 "
        "{%0,%1,%2,%3}, {%4,%5,%6,%7}, {%8,%9}, {%0,%1,%2,%3};\n"
        : "+f"(c[0]), "+f"(c[1]), "+f"(c[2]), "+f"(c[3])
        : "r"(a[0]), "r"(a[1]), "r"(a[2]), "r"(a[3]), "r"(b0), "r"(b1));
}

// Load one 64x64 K/V tile pair into a smem stage (K padded, V xor-swizzled).
__device__ __forceinline__ void preload_kv(float* dK, float* dV,
                                           const float* gk, const float* gv,
                                           size_t base, int kv0, int tid) {
    const float4* srcK = (const float4*)(gk + base + (size_t)kv0 * 64);
    const float4* srcV = (const float4*)(gv + base + (size_t)kv0 * 64);
    #pragma unroll
    for (int j = 0; j < 4; j++) {
        const int i = tid + j * 256;
        const int row = i >> 4, c4 = (i & 15) << 2;
        cpa16(dK + row * STRIDE + c4, srcK + i);
        cpa16(dV + row * 64 + (c4 ^ ((row & 7) << 3)), srcV + i);
    }
}

__global__ void __launch_bounds__(256, 2)
omni_attn_kernel(const float* __restrict__ gq, const float* __restrict__ gk,
                 const float* __restrict__ gv,
                 const int* __restrict__ gpad, const int* __restrict__ gfs,
                 const int* __restrict__ gfe,
                 const int* __restrict__ p_bt2i, const int* __restrict__ p_blm,
                 float* __restrict__ gout, int H, int S)
{
    extern __shared__ float smem[];
    float* sK   = smem;                          // 2 stages x 64 x STRIDE
    float* sV   = sK + 2 * 64 * STRIDE;          // 2 stages x 64 x 64 (swizzled)
    float* sQ   = sV + 2 * 64 * 64;              // 128 x STRIDE (persistent tf32 Q)
    int*   sPad = (int*)(sQ + 128 * STRIDE);     // 2 stages x 64
    int*   sRed = sPad + 128;                    // 16

    const int tid  = threadIdx.x;
    const int warp = tid >> 5;
    const int lane = tid & 31;
    const int g = lane >> 2;
    const int t = lane & 3;

    const int q0 = blockIdx.x * 128;
    const int bh = blockIdx.y;
    const int b  = bh / H;

    const int bt2i = p_bt2i[0];
    const int blm  = p_blm[0];
    const int mode = (b < bt2i) ? 0 : ((b < bt2i + blm) ? 1 : 2);

    const size_t base = (size_t)bh * S * 64;

    // ---- per-warp row info ----
    const int qr0 = q0 + warp * 16 + g;
    const int qr1 = qr0 + 8;
    const int wmin = q0 + warp * 16;
    int fs0 = 0, fe0 = 0, fs1 = 0, fe1 = 0;
    if (mode == 0) {
        fs0 = gfs[qr0]; fe0 = gfe[qr0];
        fs1 = gfs[qr1]; fe1 = gfe[qr1];
    }
    const int pe = (mode == 0) ? gpad[(size_t)b * S] : 0;

    // ---- data-driven kv range for this CTA ----
    int kv_end, kv_beg = 0;
    if (mode == 1) {
        kv_end = q0 + 128;
    } else if (mode == 2) {
        kv_end = q0 + 128;
        if (kv_end < 580) kv_end = 580;     // kv <= 579 always visible
    } else {
        int need = 0, strt = S;
        #pragma unroll
        for (int h = 0; h < 2; h++) {
            const int qq = h ? qr1 : qr0;
            const int ff = h ? fe1 : fe0;
            int nd = qq + 1;
            if (ff > nd) nd = ff;
            if (qq == pe) nd = S;            // empty row: count all kv
            if (nd > need) need = nd;
            int st = (qq == pe) ? 0 : ((qq < pe) ? qq : pe);
            if (st < strt) strt = st;
        }
        need = __reduce_max_sync(0xffffffffu, need);
        strt = __reduce_min_sync(0xffffffffu, strt);
        if (lane == 0) { sRed[warp] = need; sRed[8 + warp] = strt; }
        __syncthreads();
        int mx = sRed[0], mn = sRed[8];
        #pragma unroll
        for (int w = 1; w < 8; w++) {
            if (sRed[w] > mx) mx = sRed[w];
            if (sRed[8 + w] < mn) mn = sRed[8 + w];
        }
        kv_end = mx;
        kv_beg = mn & ~63;
    }
    if (kv_end > S) kv_end = S;
    const int it0 = kv_beg >> 6;
    const int itN = (kv_end + 63) >> 6;

    // ---- preload first KV tile (overlaps with Q staging below) ----
    {
        const int stg0 = it0 & 1;
        preload_kv(sK + stg0 * 64 * STRIDE, sV + stg0 * 64 * 64, gk, gv, base, it0 << 6, tid);
        if (mode == 0 && tid < 64)
            cpa4(sPad + stg0 * 64 + tid, gpad + (size_t)b * S + (it0 << 6) + tid);
        asm volatile("cp.async.commit_group;");
    }

    // ---- stage Q tile (128x64), fold scale*log2e, tf32-round ----
    {
        const float qs = 0.125f * 1.4426950408889634f;
        const float4* src = (const float4*)(gq + base + (size_t)q0 * 64);
        #pragma unroll
        for (int j = 0; j < 8; j++) {
            const int i = tid + j * 256;
            float4 x = src[i];
            float4 y;
            y.x = __uint_as_float(f2tf(x.x * qs));
            y.y = __uint_as_float(f2tf(x.y * qs));
            y.z = __uint_as_float(f2tf(x.z * qs));
            y.w = __uint_as_float(f2tf(x.w * qs));
            *(float4*)(sQ + (i >> 4) * STRIDE + ((i & 15) << 2)) = y;
        }
    }
    __syncthreads();   // Q staged

    // ---- Q fragments register-resident (one 16-row tile per warp) ----
    uint32_t qa[8][4];
    {
        const int r0s = (warp * 16 + g) * STRIDE;
        #pragma unroll
        for (int kt = 0; kt < 8; kt++) {
            qa[kt][0] = __float_as_uint(sQ[r0s              + kt * 8 + t]);
            qa[kt][1] = __float_as_uint(sQ[r0s + 8 * STRIDE + kt * 8 + t]);
            qa[kt][2] = __float_as_uint(sQ[r0s              + kt * 8 + t + 4]);
            qa[kt][3] = __float_as_uint(sQ[r0s + 8 * STRIDE + kt * 8 + t + 4]);
        }
    }

    float o[8][4];
    #pragma unroll
    for (int n = 0; n < 8; n++)
        o[n][0] = o[n][1] = o[n][2] = o[n][3] = 0.f;
    float m0 = -1e30f, m1 = -1e30f, l0 = 0.f, l1 = 0.f;

    for (int it = it0; it < itN; it++) {
        const int kv0 = it << 6;
        const int stg = it & 1;
        const float* sKs = sK + stg * 64 * STRIDE;
        const float* sVs = sV + stg * 64 * 64;
        const int*   sPs = sPad + stg * 64;

        __syncthreads();   // previous compute's reads of the other stage done
        if (it + 1 < itN) {
            const int nstg = stg ^ 1;
            preload_kv(sK + nstg * 64 * STRIDE, sV + nstg * 64 * 64, gk, gv, base, kv0 + 64, tid);
            if (mode == 0 && tid < 64)
                cpa4(sPad + nstg * 64 + tid, gpad + (size_t)b * S + kv0 + 64 + tid);
            asm volatile("cp.async.commit_group;");
            asm volatile("cp.async.wait_group 1;");
        } else {
            asm volatile("cp.async.wait_group 0;");
        }
        __syncthreads();   // tile it visible

        // ---- per-warp fully-masked-tile skip ----
        bool wskip;
        if (mode == 1) {
            wskip = kv0 > wmin + 15;
        } else if (mode == 2) {
            wskip = (kv0 > wmin + 15) && (kv0 > 579);
        } else {
            bool th_skip = true;
            #pragma unroll
            for (int h = 0; h < 2; h++) {
                const int r  = h ? qr1 : qr0;
                const int f0 = h ? fs1 : fs0;
                const int f1 = h ? fe1 : fe0;
                const bool no_caus = (kv0 > r) || (kv0 + 63 < pe);
                const bool no_full = (kv0 >= f1) || (kv0 + 63 < f0);
                const bool no_diag = (r < kv0) || (r > kv0 + 63);
                th_skip = th_skip && no_caus && no_full && no_diag && (r != pe);
            }
            wskip = __all_sync(0xffffffffu, th_skip);
        }
        if (wskip) continue;

        // ---- unmasked-tile fast path test ----
        bool nomask;
        if (mode == 1) {
            nomask = (kv0 + 63 <= wmin);
        } else if (mode == 2) {
            nomask = (kv0 + 63 <= 579) || (kv0 + 63 <= wmin);
        } else {
            bool th_nm = true;
            #pragma unroll
            for (int h = 0; h < 2; h++) {
                const int r  = h ? qr1 : qr0;
                const int f0 = h ? fs1 : fs0;
                const int f1 = h ? fe1 : fe0;
                const bool full_cov = (f0 <= kv0) && (kv0 + 63 < f1) &&
                                      (r < kv0 || r > kv0 + 63);
                const bool caus_cov = (kv0 >= pe) && (kv0 + 63 < r);
                th_nm = th_nm && (full_cov || caus_cov);
            }
            nomask = __all_sync(0xffffffffu, th_nm);
        }

        // ---- S = Q @ K^T (log2 domain, prescaled) ----
        float c[8][4];
        #pragma unroll
        for (int n = 0; n < 8; n++) {
            c[n][0] = c[n][1] = c[n][2] = c[n][3] = 0.f;
            #pragma unroll
            for (int kt = 0; kt < 8; kt++) {
                const uint32_t b0 = __float_as_uint(sKs[(n * 8 + g) * STRIDE + kt * 8 + t]);
                const uint32_t b1 = __float_as_uint(sKs[(n * 8 + g) * STRIDE + kt * 8 + t + 4]);
                mma8(c[n], qa[kt], b0, b1);
            }
        }

        // ---- mask ----
        if (!nomask) {
            #pragma unroll
            for (int n = 0; n < 8; n++) {
                const int col0 = kv0 + n * 8 + 2 * t;
                const int col1 = col0 + 1;
                bool m00, m01, m10, m11;
                if (mode == 1) {
                    m00 = qr0 >= col0; m01 = qr0 >= col1;
                    m10 = qr1 >= col0; m11 = qr1 >= col1;
                } else if (mode == 2) {
                    const bool c0c = col0 <= 579, c1c = col1 <= 579;
                    m00 = (qr0 >= col0) || c0c; m01 = (qr0 >= col1) || c1c;
                    m10 = (qr1 >= col0) || c0c; m11 = (qr1 >= col1) || c1c;
                } else {
                    const bool pad0 = col0 < sPs[n * 8 + 2 * t];
                    const bool pad1 = col1 < sPs[n * 8 + 2 * t + 1];
                    const bool f00 = (col0 < fe0) && (col0 >= fs0);
                    const bool f01 = (col1 < fe0) && (col1 >= fs0);
                    const bool f10 = (col0 < fe1) && (col0 >= fs1);
                    const bool f11 = (col1 < fe1) && (col1 >= fs1);
                    m00 = (qr0 == col0) != ((!pad0 && (qr0 >= col0)) || f00);
                    m01 = (qr0 == col1) != ((!pad1 && (qr0 >= col1)) || f01);
                    m10 = (qr1 == col0) != ((!pad0 && (qr1 >= col0)) || f10);
                    m11 = (qr1 == col1) != ((!pad1 && (qr1 >= col1)) || f11);
                }
                if (!m00) c[n][0] = -1e30f;
                if (!m01) c[n][1] = -1e30f;
                if (!m10) c[n][2] = -1e30f;
                if (!m11) c[n][3] = -1e30f;
            }
        }

        // ---- online softmax, exp2 domain (quad owns two rows) ----
        float tm0 = -1e30f, tm1 = -1e30f;
        #pragma unroll
        for (int n = 0; n < 8; n++) {
            tm0 = fmaxf(tm0, fmaxf(c[n][0], c[n][1]));
            tm1 = fmaxf(tm1, fmaxf(c[n][2], c[n][3]));
        }
        tm0 = fmaxf(tm0, __shfl_xor_sync(0xffffffffu, tm0, 1));
        tm0 = fmaxf(tm0, __shfl_xor_sync(0xffffffffu, tm0, 2));
        tm1 = fmaxf(tm1, __shfl_xor_sync(0xffffffffu, tm1, 1));
        tm1 = fmaxf(tm1, __shfl_xor_sync(0xffffffffu, tm1, 2));
        const float mn0 = fmaxf(m0, tm0), mn1 = fmaxf(m1, tm1);
        const float al0 = ex2f(m0 - mn0), al1 = ex2f(m1 - mn1);
        float s0 = 0.f, s1 = 0.f;
        #pragma unroll
        for (int n = 0; n < 8; n++) {
            c[n][0] = ex2f(c[n][0] - mn0);
            c[n][1] = ex2f(c[n][1] - mn0);
            c[n][2] = ex2f(c[n][2] - mn1);
            c[n][3] = ex2f(c[n][3] - mn1);
            s0 += c[n][0] + c[n][1];
            s1 += c[n][2] + c[n][3];
        }
        s0 += __shfl_xor_sync(0xffffffffu, s0, 1);
        s0 += __shfl_xor_sync(0xffffffffu, s0, 2);
        s1 += __shfl_xor_sync(0xffffffffu, s1, 1);
        s1 += __shfl_xor_sync(0xffffffffu, s1, 2);
        l0 = l0 * al0 + s0;
        l1 = l1 * al1 + s1;
        m0 = mn0; m1 = mn1;
        #pragma unroll
        for (int n = 0; n < 8; n++) {
            o[n][0] *= al0; o[n][1] *= al0;
            o[n][2] *= al1; o[n][3] *= al1;
        }

        // ---- O += P @ V with in-register quad-shuffle transpose of P ----
        const int src0 = (lane & ~3) | (t >> 1);
        const bool odd = (t & 1);
        #pragma unroll
        for (int kt = 0; kt < 8; kt++) {
            const float x0 = __shfl_sync(0xffffffffu, c[kt][0], src0);
            const float x1 = __shfl_sync(0xffffffffu, c[kt][1], src0);
            const float y0 = __shfl_sync(0xffffffffu, c[kt][2], src0);
            const float y1 = __shfl_sync(0xffffffffu, c[kt][3], src0);
            const float z0 = __shfl_sync(0xffffffffu, c[kt][0], src0 + 2);
            const float z1 = __shfl_sync(0xffffffffu, c[kt][1], src0 + 2);
            const float w0 = __shfl_sync(0xffffffffu, c[kt][2], src0 + 2);
            const float w1 = __shfl_sync(0xffffffffu, c[kt][3], src0 + 2);
            uint32_t pa[4];
            pa[0] = __float_as_uint(odd ? x1 : x0);   // P[g   ][8kt+t]
            pa[1] = __float_as_uint(odd ? y1 : y0);   // P[g+8 ][8kt+t]
            pa[2] = __float_as_uint(odd ? z1 : z0);   // P[g   ][8kt+t+4]
            pa[3] = __float_as_uint(odd ? w1 : w0);   // P[g+8 ][8kt+t+4]

            const int vr0 = (8 * kt + t) * 64 + g;
            const int vr1 = (8 * kt + t + 4) * 64 + g;
            #pragma unroll
            for (int n = 0; n < 8; n++) {
                const uint32_t b0 = __float_as_uint(sVs[vr0 + 8 * (n ^ t)]);
                const uint32_t b1 = __float_as_uint(sVs[vr1 + 8 * ((n ^ t) ^ 4)]);
                mma8(o[n], pa, b0, b1);
            }
        }
    }

    // ---- epilogue ----
    const float inv0 = 1.f / l0, inv1 = 1.f / l1;
    float* orow0 = gout + base + (size_t)qr0 * 64;
    float* orow1 = gout + base + (size_t)qr1 * 64;
    #pragma unroll
    for (int n = 0; n < 8; n++) {
        float2 w0 = make_float2(o[n][0] * inv0, o[n][1] * inv0);
        float2 w1 = make_float2(o[n][2] * inv1, o[n][3] * inv1);
        *(float2*)(orow0 + n * 8 + 2 * t) = w0;
        *(float2*)(orow1 + n * 8 + 2 * t) = w1;
    }
}

extern "C" void kernel_launch(void* const* d_in, const int* in_sizes, int n_in,
                              void* d_out, int out_size)
{
    const float* q   = (const float*)d_in[0];
    const float* k   = (const float*)d_in[1];
    const float* v   = (const float*)d_in[2];
    const int* pad   = (const int*)d_in[3];
    const int* fs    = (const int*)d_in[4];
    const int* fe    = (const int*)d_in[5];
    const int* bt2i  = (const int*)d_in[6];
    const int* blm   = (const int*)d_in[7];
    float* out = (float*)d_out;

    const int S = in_sizes[4];
    const int B = in_sizes[3] / S;
    const int H = (int)((long long)in_sizes[0] / ((long long)B * S * 64));

    const size_t smem_bytes =
        (size_t)(2 * 64 * STRIDE + 2 * 64 * 64 + 128 * STRIDE) * sizeof(float)
        + 144 * sizeof(int);
    cudaFuncSetAttribute(omni_attn_kernel,
                         cudaFuncAttributeMaxDynamicSharedMemorySize, (int)smem_bytes);

    dim3 grid(S / 128, B * H);
    omni_attn_kernel<<<grid, 256, smem_bytes>>>(q, k, v, pad, fs, fe, bt2i, blm, out, H, S);
}

// round 7
// speedup vs baseline: 1.9579x; 1.0841x over previous
#include <cuda_runtime.h>
#include <cstdint>

// OmniAttention flash-forward, tf32 mma.sync.
// 256 threads/CTA (8 warps), 16 q-rows per warp. KV_TILE=64 double-buffered
// cp.async, 2 CTAs/SM. P C-fragments feed PV mma DIRECTLY (no transpose):
// V rows are permuted in smem (row v -> (v&1)*4 + (v>>1) within 8-row groups)
// so the hardware contraction index stays consistent. exp2-domain softmax,
// exact mask tile skipping.

#define STRIDE 68  // padded smem row stride (words) for K / Q

__device__ __forceinline__ uint32_t f2tf(float x) {
    uint32_t r;
    asm("cvt.rna.tf32.f32 %0, %1;" : "=r"(r) : "f"(x));
    return r;
}
__device__ __forceinline__ float ex2f(float x) {
    float y;
    asm("ex2.approx.f32 %0, %1;" : "=f"(y) : "f"(x));
    return y;
}
__device__ __forceinline__ void cpa16(void* dst, const void* src) {
    uint32_t d = (uint32_t)__cvta_generic_to_shared(dst);
    asm volatile("cp.async.cg.shared.global [%0], [%1], 16;" :: "r"(d), "l"(src));
}
__device__ __forceinline__ void cpa4(void* dst, const void* src) {
    uint32_t d = (uint32_t)__cvta_generic_to_shared(dst);
    asm volatile("cp.async.ca.shared.global [%0], [%1], 4;" :: "r"(d), "l"(src));
}
__device__ __forceinline__ void mma8(float* c, const uint32_t* a, uint32_t b0, uint32_t b1) {
    asm volatile(
        "mma.sync.aligned.m16n8k8.row.col.f32.tf32.tf32.f32 "
        "{%0,%1,%2,%3}, {%4,%5,%6,%7}, {%8,%9}, {%0,%1,%2,%3};\n"
        : "+f"(c[0]), "+f"(c[1]), "+f"(c[2]), "+f"(c[3])
        : "r"(a[0]), "r"(a[1]), "r"(a[2]), "r"(a[3]), "r"(b0), "r"(b1));
}

// Load one 64x64 K/V tile pair into a smem stage.
// K: padded rows, natural order. V: xor-swizzled, rows permuted within each
// 8-row group by psi(v) = (v&1)*4 + (v>>1)  (psi = phi^-1 for the direct
// C-frag -> A-frag feed in the PV mma).
__device__ __forceinline__ void preload_kv(float* dK, float* dV,
                                           const float* gk, const float* gv,
                                           size_t base, int kv0, int tid) {
    const float4* srcK = (const float4*)(gk + base + (size_t)kv0 * 64);
    const float4* srcV = (const float4*)(gv + base + (size_t)kv0 * 64);
    #pragma unroll
    for (int j = 0; j < 4; j++) {
        const int i = tid + j * 256;
        const int row = i >> 4, c4 = (i & 15) << 2;
        cpa16(dK + row * STRIDE + c4, srcK + i);
        const int prow = (row & ~7) | (((row & 1) << 2) | ((row & 7) >> 1));
        cpa16(dV + prow * 64 + (c4 ^ ((prow & 7) << 3)), srcV + i);
    }
}

__global__ void __launch_bounds__(256, 2)
omni_attn_kernel(const float* __restrict__ gq, const float* __restrict__ gk,
                 const float* __restrict__ gv,
                 const int* __restrict__ gpad, const int* __restrict__ gfs,
                 const int* __restrict__ gfe,
                 const int* __restrict__ p_bt2i, const int* __restrict__ p_blm,
                 float* __restrict__ gout, int H, int S)
{
    extern __shared__ float smem[];
    float* sK   = smem;                          // 2 stages x 64 x STRIDE
    float* sV   = sK + 2 * 64 * STRIDE;          // 2 stages x 64 x 64 (swizzled+permuted)
    float* sQ   = sV + 2 * 64 * 64;              // 128 x STRIDE (persistent tf32 Q)
    int*   sPad = (int*)(sQ + 128 * STRIDE);     // 2 stages x 64
    int*   sRed = sPad + 128;                    // 16

    const int tid  = threadIdx.x;
    const int warp = tid >> 5;
    const int lane = tid & 31;
    const int g = lane >> 2;
    const int t = lane & 3;

    const int q0 = blockIdx.x * 128;
    const int bh = blockIdx.y;
    const int b  = bh / H;

    const int bt2i = p_bt2i[0];
    const int blm  = p_blm[0];
    const int mode = (b < bt2i) ? 0 : ((b < bt2i + blm) ? 1 : 2);

    const size_t base = (size_t)bh * S * 64;

    // ---- per-warp row info ----
    const int qr0 = q0 + warp * 16 + g;
    const int qr1 = qr0 + 8;
    const int wmin = q0 + warp * 16;
    int fs0 = 0, fe0 = 0, fs1 = 0, fe1 = 0;
    if (mode == 0) {
        fs0 = gfs[qr0]; fe0 = gfe[qr0];
        fs1 = gfs[qr1]; fe1 = gfe[qr1];
    }
    const int pe = (mode == 0) ? gpad[(size_t)b * S] : 0;

    // ---- data-driven kv range for this CTA ----
    int kv_end, kv_beg = 0;
    if (mode == 1) {
        kv_end = q0 + 128;
    } else if (mode == 2) {
        kv_end = q0 + 128;
        if (kv_end < 580) kv_end = 580;     // kv <= 579 always visible
    } else {
        int need = 0, strt = S;
        #pragma unroll
        for (int h = 0; h < 2; h++) {
            const int qq = h ? qr1 : qr0;
            const int ff = h ? fe1 : fe0;
            int nd = qq + 1;
            if (ff > nd) nd = ff;
            if (qq == pe) nd = S;            // empty row: count all kv
            if (nd > need) need = nd;
            int st = (qq == pe) ? 0 : ((qq < pe) ? qq : pe);
            if (st < strt) strt = st;
        }
        need = __reduce_max_sync(0xffffffffu, need);
        strt = __reduce_min_sync(0xffffffffu, strt);
        if (lane == 0) { sRed[warp] = need; sRed[8 + warp] = strt; }
        __syncthreads();
        int mx = sRed[0], mn = sRed[8];
        #pragma unroll
        for (int w = 1; w < 8; w++) {
            if (sRed[w] > mx) mx = sRed[w];
            if (sRed[8 + w] < mn) mn = sRed[8 + w];
        }
        kv_end = mx;
        kv_beg = mn & ~63;
    }
    if (kv_end > S) kv_end = S;
    const int it0 = kv_beg >> 6;
    const int itN = (kv_end + 63) >> 6;

    // ---- preload first KV tile (overlaps with Q staging below) ----
    {
        const int stg0 = it0 & 1;
        preload_kv(sK + stg0 * 64 * STRIDE, sV + stg0 * 64 * 64, gk, gv, base, it0 << 6, tid);
        if (mode == 0 && tid < 64)
            cpa4(sPad + stg0 * 64 + tid, gpad + (size_t)b * S + (it0 << 6) + tid);
        asm volatile("cp.async.commit_group;");
    }

    // ---- stage Q tile (128x64), fold scale*log2e, tf32-round ----
    {
        const float qs = 0.125f * 1.4426950408889634f;
        const float4* src = (const float4*)(gq + base + (size_t)q0 * 64);
        #pragma unroll
        for (int j = 0; j < 8; j++) {
            const int i = tid + j * 256;
            float4 x = src[i];
            float4 y;
            y.x = __uint_as_float(f2tf(x.x * qs));
            y.y = __uint_as_float(f2tf(x.y * qs));
            y.z = __uint_as_float(f2tf(x.z * qs));
            y.w = __uint_as_float(f2tf(x.w * qs));
            *(float4*)(sQ + (i >> 4) * STRIDE + ((i & 15) << 2)) = y;
        }
    }
    __syncthreads();   // Q staged

    // ---- Q fragments register-resident (one 16-row tile per warp) ----
    uint32_t qa[8][4];
    {
        const int r0s = (warp * 16 + g) * STRIDE;
        #pragma unroll
        for (int kt = 0; kt < 8; kt++) {
            qa[kt][0] = __float_as_uint(sQ[r0s              + kt * 8 + t]);
            qa[kt][1] = __float_as_uint(sQ[r0s + 8 * STRIDE + kt * 8 + t]);
            qa[kt][2] = __float_as_uint(sQ[r0s              + kt * 8 + t + 4]);
            qa[kt][3] = __float_as_uint(sQ[r0s + 8 * STRIDE + kt * 8 + t + 4]);
        }
    }

    float o[8][4];
    #pragma unroll
    for (int n = 0; n < 8; n++)
        o[n][0] = o[n][1] = o[n][2] = o[n][3] = 0.f;
    float m0 = -1e30f, m1 = -1e30f, l0 = 0.f, l1 = 0.f;

    for (int it = it0; it < itN; it++) {
        const int kv0 = it << 6;
        const int stg = it & 1;
        const float* sKs = sK + stg * 64 * STRIDE;
        const float* sVs = sV + stg * 64 * 64;
        const int*   sPs = sPad + stg * 64;

        __syncthreads();   // previous compute's reads of the other stage done
        if (it + 1 < itN) {
            const int nstg = stg ^ 1;
            preload_kv(sK + nstg * 64 * STRIDE, sV + nstg * 64 * 64, gk, gv, base, kv0 + 64, tid);
            if (mode == 0 && tid < 64)
                cpa4(sPad + nstg * 64 + tid, gpad + (size_t)b * S + kv0 + 64 + tid);
            asm volatile("cp.async.commit_group;");
            asm volatile("cp.async.wait_group 1;");
        } else {
            asm volatile("cp.async.wait_group 0;");
        }
        __syncthreads();   // tile it visible

        // ---- per-warp fully-masked-tile skip ----
        bool wskip;
        if (mode == 1) {
            wskip = kv0 > wmin + 15;
        } else if (mode == 2) {
            wskip = (kv0 > wmin + 15) && (kv0 > 579);
        } else {
            bool th_skip = true;
            #pragma unroll
            for (int h = 0; h < 2; h++) {
                const int r  = h ? qr1 : qr0;
                const int f0 = h ? fs1 : fs0;
                const int f1 = h ? fe1 : fe0;
                const bool no_caus = (kv0 > r) || (kv0 + 63 < pe);
                const bool no_full = (kv0 >= f1) || (kv0 + 63 < f0);
                const bool no_diag = (r < kv0) || (r > kv0 + 63);
                th_skip = th_skip && no_caus && no_full && no_diag && (r != pe);
            }
            wskip = __all_sync(0xffffffffu, th_skip);
        }
        if (wskip) continue;

        // ---- unmasked-tile fast path test ----
        bool nomask;
        if (mode == 1) {
            nomask = (kv0 + 63 <= wmin);
        } else if (mode == 2) {
            nomask = (kv0 + 63 <= 579) || (kv0 + 63 <= wmin);
        } else {
            bool th_nm = true;
            #pragma unroll
            for (int h = 0; h < 2; h++) {
                const int r  = h ? qr1 : qr0;
                const int f0 = h ? fs1 : fs0;
                const int f1 = h ? fe1 : fe0;
                const bool full_cov = (f0 <= kv0) && (kv0 + 63 < f1) &&
                                      (r < kv0 || r > kv0 + 63);
                const bool caus_cov = (kv0 >= pe) && (kv0 + 63 < r);
                th_nm = th_nm && (full_cov || caus_cov);
            }
            nomask = __all_sync(0xffffffffu, th_nm);
        }

        // ---- S = Q @ K^T (log2 domain, prescaled) ----
        float c[8][4];
        #pragma unroll
        for (int n = 0; n < 8; n++) {
            c[n][0] = c[n][1] = c[n][2] = c[n][3] = 0.f;
            #pragma unroll
            for (int kt = 0; kt < 8; kt++) {
                const uint32_t b0 = __float_as_uint(sKs[(n * 8 + g) * STRIDE + kt * 8 + t]);
                const uint32_t b1 = __float_as_uint(sKs[(n * 8 + g) * STRIDE + kt * 8 + t + 4]);
                mma8(c[n], qa[kt], b0, b1);
            }
        }

        // ---- mask ----
        if (!nomask) {
            #pragma unroll
            for (int n = 0; n < 8; n++) {
                const int col0 = kv0 + n * 8 + 2 * t;
                const int col1 = col0 + 1;
                bool m00, m01, m10, m11;
                if (mode == 1) {
                    m00 = qr0 >= col0; m01 = qr0 >= col1;
                    m10 = qr1 >= col0; m11 = qr1 >= col1;
                } else if (mode == 2) {
                    const bool c0c = col0 <= 579, c1c = col1 <= 579;
                    m00 = (qr0 >= col0) || c0c; m01 = (qr0 >= col1) || c1c;
                    m10 = (qr1 >= col0) || c0c; m11 = (qr1 >= col1) || c1c;
                } else {
                    const bool pad0 = col0 < sPs[n * 8 + 2 * t];
                    const bool pad1 = col1 < sPs[n * 8 + 2 * t + 1];
                    const bool f00 = (col0 < fe0) && (col0 >= fs0);
                    const bool f01 = (col1 < fe0) && (col1 >= fs0);
                    const bool f10 = (col0 < fe1) && (col0 >= fs1);
                    const bool f11 = (col1 < fe1) && (col1 >= fs1);
                    m00 = (qr0 == col0) != ((!pad0 && (qr0 >= col0)) || f00);
                    m01 = (qr0 == col1) != ((!pad1 && (qr0 >= col1)) || f01);
                    m10 = (qr1 == col0) != ((!pad0 && (qr1 >= col0)) || f10);
                    m11 = (qr1 == col1) != ((!pad1 && (qr1 >= col1)) || f11);
                }
                if (!m00) c[n][0] = -1e30f;
                if (!m01) c[n][1] = -1e30f;
                if (!m10) c[n][2] = -1e30f;
                if (!m11) c[n][3] = -1e30f;
            }
        }

        // ---- online softmax, exp2 domain (quad owns two rows) ----
        float tm0 = -1e30f, tm1 = -1e30f;
        #pragma unroll
        for (int n = 0; n < 8; n++) {
            tm0 = fmaxf(tm0, fmaxf(c[n][0], c[n][1]));
            tm1 = fmaxf(tm1, fmaxf(c[n][2], c[n][3]));
        }
        tm0 = fmaxf(tm0, __shfl_xor_sync(0xffffffffu, tm0, 1));
        tm0 = fmaxf(tm0, __shfl_xor_sync(0xffffffffu, tm0, 2));
        tm1 = fmaxf(tm1, __shfl_xor_sync(0xffffffffu, tm1, 1));
        tm1 = fmaxf(tm1, __shfl_xor_sync(0xffffffffu, tm1, 2));
        const float mn0 = fmaxf(m0, tm0), mn1 = fmaxf(m1, tm1);
        const float al0 = ex2f(m0 - mn0), al1 = ex2f(m1 - mn1);
        float s0 = 0.f, s1 = 0.f;
        #pragma unroll
        for (int n = 0; n < 8; n++) {
            c[n][0] = ex2f(c[n][0] - mn0);
            c[n][1] = ex2f(c[n][1] - mn0);
            c[n][2] = ex2f(c[n][2] - mn1);
            c[n][3] = ex2f(c[n][3] - mn1);
            s0 += c[n][0] + c[n][1];
            s1 += c[n][2] + c[n][3];
        }
        s0 += __shfl_xor_sync(0xffffffffu, s0, 1);
        s0 += __shfl_xor_sync(0xffffffffu, s0, 2);
        s1 += __shfl_xor_sync(0xffffffffu, s1, 1);
        s1 += __shfl_xor_sync(0xffffffffu, s1, 2);
        l0 = l0 * al0 + s0;
        l1 = l1 * al1 + s1;
        m0 = mn0; m1 = mn1;
        // Skip the 64-FMA rescale when no lane's max changed (al==1 exactly).
        if (!__all_sync(0xffffffffu, (al0 == 1.0f) & (al1 == 1.0f))) {
            #pragma unroll
            for (int n = 0; n < 8; n++) {
                o[n][0] *= al0; o[n][1] *= al0;
                o[n][2] *= al1; o[n][3] *= al1;
            }
        }

        // ---- O += P @ V : C-frags feed directly as A-frags (V rows permuted) ----
        #pragma unroll
        for (int kt = 0; kt < 8; kt++) {
            uint32_t pa[4];
            pa[0] = __float_as_uint(c[kt][0]);   // A[g   ][hw t  ] = P[g][2t]
            pa[1] = __float_as_uint(c[kt][2]);   // A[g+8 ][hw t  ] = P[g+8][2t]
            pa[2] = __float_as_uint(c[kt][1]);   // A[g   ][hw t+4] = P[g][2t+1]
            pa[3] = __float_as_uint(c[kt][3]);   // A[g+8 ][hw t+4] = P[g+8][2t+1]

            const int vr0 = (8 * kt + t) * 64 + g;       // physical (permuted) rows
            const int vr1 = (8 * kt + t + 4) * 64 + g;
            #pragma unroll
            for (int n = 0; n < 8; n++) {
                const uint32_t b0 = __float_as_uint(sVs[vr0 + 8 * (n ^ t)]);
                const uint32_t b1 = __float_as_uint(sVs[vr1 + 8 * ((n ^ t) ^ 4)]);
                mma8(o[n], pa, b0, b1);
            }
        }
    }

    // ---- epilogue ----
    const float inv0 = 1.f / l0, inv1 = 1.f / l1;
    float* orow0 = gout + base + (size_t)qr0 * 64;
    float* orow1 = gout + base + (size_t)qr1 * 64;
    #pragma unroll
    for (int n = 0; n < 8; n++) {
        float2 w0 = make_float2(o[n][0] * inv0, o[n][1] * inv0);
        float2 w1 = make_float2(o[n][2] * inv1, o[n][3] * inv1);
        *(float2*)(orow0 + n * 8 + 2 * t) = w0;
        *(float2*)(orow1 + n * 8 + 2 * t) = w1;
    }
}

extern "C" void kernel_launch(void* const* d_in, const int* in_sizes, int n_in,
                              void* d_out, int out_size)
{
    const float* q   = (const float*)d_in[0];
    const float* k   = (const float*)d_in[1];
    const float* v   = (const float*)d_in[2];
    const int* pad   = (const int*)d_in[3];
    const int* fs    = (const int*)d_in[4];
    const int* fe    = (const int*)d_in[5];
    const int* bt2i  = (const int*)d_in[6];
    const int* blm   = (const int*)d_in[7];
    float* out = (float*)d_out;

    const int S = in_sizes[4];
    const int B = in_sizes[3] / S;
    const int H = (int)((long long)in_sizes[0] / ((long long)B * S * 64));

    const size_t smem_bytes =
        (size_t)(2 * 64 * STRIDE + 2 * 64 * 64 + 128 * STRIDE) * sizeof(float)
        + 144 * sizeof(int);
    cudaFuncSetAttribute(omni_attn_kernel,
                         cudaFuncAttributeMaxDynamicSharedMemorySize, (int)smem_bytes);

    dim3 grid(S / 128, B * H);
    omni_attn_kernel<<<grid, 256, smem_bytes>>>(q, k, v, pad, fs, fe, bt2i, blm, out, H, S);
}

// round 9
// speedup vs baseline: 2.5050x; 1.2794x over previous
#include <cuda_runtime.h>
#include <cuda_fp16.h>
#include <cstdint>

// OmniAttention flash-forward, fp16 mma.sync (m16n8k16, fp32 accum).
// Pre-pass kernel converts K -> fp16 (natural layout) and V -> fp16 TRANSPOSED
// (d-major) into __device__ scratch. Main kernel: 256 thr/CTA, 16 q-rows/warp,
// KV_TILE=64, 3-stage cp.async ring (1 barrier/tile, prefetch distance 2),
// P C-frags feed PV directly via f16x2 packing, exp2 softmax, exact tile skip.

#define SH 36              // words per fp16 row: 64 halfs = 32 words + 4 pad
#define STG_W (64 * SH)    // words per 64-row tile stage
#define MAXE 6291456       // B*H*S*D elements for this problem (12*8*1024*64)

__device__ __align__(16) __half g_k16[MAXE];    // K as fp16, [bh][s][d]
__device__ __align__(16) __half g_vt16[MAXE];   // V^T as fp16, [bh][d][s]

__device__ __forceinline__ float ex2f(float x) {
    float y;
    asm("ex2.approx.f32 %0, %1;" : "=f"(y) : "f"(x));
    return y;
}
__device__ __forceinline__ uint32_t packh2(float lo, float hi) {
    uint32_t r;
    asm("cvt.rn.f16x2.f32 %0, %1, %2;" : "=r"(r) : "f"(hi), "f"(lo));
    return r;
}
__device__ __forceinline__ void cpa16(void* dst, const void* src) {
    uint32_t d = (uint32_t)__cvta_generic_to_shared(dst);
    asm volatile("cp.async.cg.shared.global [%0], [%1], 16;" :: "r"(d), "l"(src));
}
__device__ __forceinline__ void cpa4(void* dst, const void* src) {
    uint32_t d = (uint32_t)__cvta_generic_to_shared(dst);
    asm volatile("cp.async.ca.shared.global [%0], [%1], 4;" :: "r"(d), "l"(src));
}
__device__ __forceinline__ void mma16(float* d, const uint32_t* a, uint32_t b0, uint32_t b1) {
    asm volatile(
        "mma.sync.aligned.m16n8k16.row.col.f32.f16.f16.f32 "
        "{%0,%1,%2,%3}, {%4,%5,%6,%7}, {%8,%9}, {%0,%1,%2,%3};\n"
        : "+f"(d[0]), "+f"(d[1]), "+f"(d[2]), "+f"(d[3])
        : "r"(a[0]), "r"(a[1]), "r"(a[2]), "r"(a[3]), "r"(b0), "r"(b1));
}

// ---------------- pre-pass: K -> fp16, V -> fp16 transposed ----------------
__global__ void __launch_bounds__(256)
prep_kernel(const float* __restrict__ gk, const float* __restrict__ gv, int S)
{
    __shared__ float tile[64][65];
    const int tid = threadIdx.x;
    const int bh  = blockIdx.y;
    const int s0  = blockIdx.x * 64;
    const size_t base = (size_t)bh * S * 64;

    // 64 rows x 16 float4/row = 1024 items = 256 threads x 4
    #pragma unroll
    for (int j = 0; j < 4; j++) {
        const int i = tid + j * 256;
        const int row = i >> 4, c4 = (i & 15) << 2;
        const size_t off = base + (size_t)(s0 + row) * 64 + c4;
        float4 xk = *(const float4*)(gk + off);
        uint2 u;
        u.x = packh2(xk.x, xk.y);
        u.y = packh2(xk.z, xk.w);
        *(uint2*)(g_k16 + off) = u;
        float4 xv = *(const float4*)(gv + off);
        tile[row][c4 + 0] = xv.x;
        tile[row][c4 + 1] = xv.y;
        tile[row][c4 + 2] = xv.z;
        tile[row][c4 + 3] = xv.w;
    }
    __syncthreads();
    // write V^T: 64 d-rows x 64 s-cols as 512 uint4 (8 halfs each)
    #pragma unroll
    for (int j = 0; j < 2; j++) {
        const int u2 = tid + j * 256;
        const int d  = u2 >> 3;
        const int sl = (u2 & 7) * 8;
        uint4 w;
        w.x = packh2(tile[sl + 0][d], tile[sl + 1][d]);
        w.y = packh2(tile[sl + 2][d], tile[sl + 3][d]);
        w.z = packh2(tile[sl + 4][d], tile[sl + 5][d]);
        w.w = packh2(tile[sl + 6][d], tile[sl + 7][d]);
        *(uint4*)(g_vt16 + ((size_t)bh * 64 + d) * S + s0 + sl) = w;
    }
}

// ---------------- main kernel ----------------
__global__ void __launch_bounds__(256, 2)
omni_attn_kernel(const float* __restrict__ gq,
                 const int* __restrict__ gpad, const int* __restrict__ gfs,
                 const int* __restrict__ gfe,
                 const int* __restrict__ p_bt2i, const int* __restrict__ p_blm,
                 float* __restrict__ gout, int H, int S)
{
    extern __shared__ uint32_t smw[];
    // [0, 3*STG_W)           : K stages (fp16, SH words/row)
    // [3*STG_W, 6*STG_W)     : V^T stages
    // [6*STG_W, +128*SH)     : Q (fp16, prescaled)
    uint32_t* sQw  = smw + 6 * STG_W;
    int*      sPad = (int*)(sQw + 128 * SH);   // 3 stages x 64
    int*      sRed = sPad + 192;               // 16

    const int tid  = threadIdx.x;
    const int warp = tid >> 5;
    const int lane = tid & 31;
    const int g = lane >> 2;
    const int t = lane & 3;

    const int q0 = blockIdx.x * 128;
    const int bh = blockIdx.y;
    const int b  = bh / H;

    const int bt2i = p_bt2i[0];
    const int blm  = p_blm[0];
    const int mode = (b < bt2i) ? 0 : ((b < bt2i + blm) ? 1 : 2);

    const size_t base = (size_t)bh * S * 64;

    // ---- per-warp row info ----
    const int qr0 = q0 + warp * 16 + g;
    const int qr1 = qr0 + 8;
    const int wmin = q0 + warp * 16;
    int fs0 = 0, fe0 = 0, fs1 = 0, fe1 = 0;
    if (mode == 0) {
        fs0 = gfs[qr0]; fe0 = gfe[qr0];
        fs1 = gfs[qr1]; fe1 = gfe[qr1];
    }
    const int pe = (mode == 0) ? gpad[(size_t)b * S] : 0;

    // ---- data-driven kv range ----
    int kv_end, kv_beg = 0;
    if (mode == 1) {
        kv_end = q0 + 128;
    } else if (mode == 2) {
        kv_end = q0 + 128;
        if (kv_end < 580) kv_end = 580;
    } else {
        int need = 0, strt = S;
        #pragma unroll
        for (int h = 0; h < 2; h++) {
            const int qq = h ? qr1 : qr0;
            const int ff = h ? fe1 : fe0;
            int nd = qq + 1;
            if (ff > nd) nd = ff;
            if (qq == pe) nd = S;
            if (nd > need) need = nd;
            int st = (qq == pe) ? 0 : ((qq < pe) ? qq : pe);
            if (st < strt) strt = st;
        }
        need = __reduce_max_sync(0xffffffffu, need);
        strt = __reduce_min_sync(0xffffffffu, strt);
        if (lane == 0) { sRed[warp] = need; sRed[8 + warp] = strt; }
        __syncthreads();
        int mx = sRed[0], mn = sRed[8];
        #pragma unroll
        for (int w = 1; w < 8; w++) {
            if (sRed[w] > mx) mx = sRed[w];
            if (sRed[8 + w] < mn) mn = sRed[8 + w];
        }
        kv_end = mx;
        kv_beg = mn & ~63;
        __syncthreads();
    }
    if (kv_end > S) kv_end = S;
    const int it0 = kv_beg >> 6;
    const int itN = (kv_end + 63) >> 6;

    // ---- stage loader (fp16 K tile + fp16 V^T tile into ring stage) ----
    auto load_stage = [&](int s, int kv0) {
        uint32_t* dK = smw + s * STG_W;
        uint32_t* dV = smw + 3 * STG_W + s * STG_W;
        const __half* srcK = g_k16 + (base + (size_t)kv0 * 64);
        const __half* srcV = g_vt16 + (size_t)bh * 64 * S + kv0;
        #pragma unroll
        for (int j = 0; j < 2; j++) {
            const int i = tid + j * 256;
            const int row = i >> 3, ch = i & 7;
            cpa16(dK + row * SH + ch * 4, srcK + row * 64 + ch * 8);
            cpa16(dV + row * SH + ch * 4, srcV + (size_t)row * S + ch * 8);
        }
        if (mode == 0 && tid < 64)
            cpa4(sPad + s * 64 + tid, gpad + (size_t)b * S + kv0 + tid);
    };

    // ---- prologue: prefetch up to 2 tiles ----
    load_stage(it0 % 3, it0 << 6);
    asm volatile("cp.async.commit_group;");
    if (it0 + 1 < itN) {
        load_stage((it0 + 1) % 3, (it0 + 1) << 6);
        asm volatile("cp.async.commit_group;");
    }

    // ---- stage Q (128x64), fold scale*log2e, convert to fp16 ----
    {
        const float qs = 0.125f * 1.4426950408889634f;
        const float4* src = (const float4*)(gq + base + (size_t)q0 * 64);
        #pragma unroll
        for (int j = 0; j < 8; j++) {
            const int i = tid + j * 256;
            const int row = i >> 4, c4 = (i & 15) << 2;
            float4 x = src[i];
            uint2 u;
            u.x = packh2(x.x * qs, x.y * qs);
            u.y = packh2(x.z * qs, x.w * qs);
            *(uint2*)(sQw + row * SH + (c4 >> 1)) = u;
        }
    }
    __syncthreads();

    // ---- Q fragments (fp16 packed), register-resident ----
    uint32_t qa[4][4];
    {
        const int r0s = (warp * 16 + g) * SH;
        #pragma unroll
        for (int kc = 0; kc < 4; kc++) {
            qa[kc][0] = sQw[r0s          + 8 * kc + t];
            qa[kc][1] = sQw[r0s + 8 * SH + 8 * kc + t];
            qa[kc][2] = sQw[r0s          + 8 * kc + t + 4];
            qa[kc][3] = sQw[r0s + 8 * SH + 8 * kc + t + 4];
        }
    }

    float o[8][4];
    #pragma unroll
    for (int n = 0; n < 8; n++)
        o[n][0] = o[n][1] = o[n][2] = o[n][3] = 0.f;
    float m0 = -1e30f, m1 = -1e30f, l0 = 0.f, l1 = 0.f;

    for (int it = it0; it < itN; it++) {
        const int kv0 = it << 6;
        const int stg = it % 3;
        const uint32_t* sKs = smw + stg * STG_W;
        const uint32_t* sVs = smw + 3 * STG_W + stg * STG_W;
        const int*      sPs = sPad + stg * 64;

        if (it + 1 < itN) asm volatile("cp.async.wait_group 1;");
        else              asm volatile("cp.async.wait_group 0;");
        __syncthreads();   // tile it visible; stage (it+2)%3 reads (iter it-1) done
        if (it + 2 < itN) {
            load_stage((it + 2) % 3, (it + 2) << 6);
            asm volatile("cp.async.commit_group;");
        }

        // ---- per-warp fully-masked-tile skip ----
        bool wskip;
        if (mode == 1) {
            wskip = kv0 > wmin + 15;
        } else if (mode == 2) {
            wskip = (kv0 > wmin + 15) && (kv0 > 579);
        } else {
            bool th_skip = true;
            #pragma unroll
            for (int h = 0; h < 2; h++) {
                const int r  = h ? qr1 : qr0;
                const int f0 = h ? fs1 : fs0;
                const int f1 = h ? fe1 : fe0;
                const bool no_caus = (kv0 > r) || (kv0 + 63 < pe);
                const bool no_full = (kv0 >= f1) || (kv0 + 63 < f0);
                const bool no_diag = (r < kv0) || (r > kv0 + 63);
                th_skip = th_skip && no_caus && no_full && no_diag && (r != pe);
            }
            wskip = __all_sync(0xffffffffu, th_skip);
        }
        if (wskip) continue;

        // ---- unmasked-tile fast path ----
        bool nomask;
        if (mode == 1) {
            nomask = (kv0 + 63 <= wmin);
        } else if (mode == 2) {
            nomask = (kv0 + 63 <= 579) || (kv0 + 63 <= wmin);
        } else {
            bool th_nm = true;
            #pragma unroll
            for (int h = 0; h < 2; h++) {
                const int r  = h ? qr1 : qr0;
                const int f0 = h ? fs1 : fs0;
                const int f1 = h ? fe1 : fe0;
                const bool full_cov = (f0 <= kv0) && (kv0 + 63 < f1) &&
                                      (r < kv0 || r > kv0 + 63);
                const bool caus_cov = (kv0 >= pe) && (kv0 + 63 < r);
                th_nm = th_nm && (full_cov || caus_cov);
            }
            nomask = __all_sync(0xffffffffu, th_nm);
        }

        // ---- S = Q @ K^T (fp16 m16n8k16, log2 domain) ----
        float c[8][4];
        #pragma unroll
        for (int n = 0; n < 8; n++) {
            c[n][0] = c[n][1] = c[n][2] = c[n][3] = 0.f;
            const int kb = (8 * n + g) * SH;
            #pragma unroll
            for (int kc = 0; kc < 4; kc++) {
                const uint32_t b0 = sKs[kb + 8 * kc + t];
                const uint32_t b1 = sKs[kb + 8 * kc + t + 4];
                mma16(c[n], qa[kc], b0, b1);
            }
        }

        // ---- mask ----
        if (!nomask) {
            #pragma unroll
            for (int n = 0; n < 8; n++) {
                const int col0 = kv0 + n * 8 + 2 * t;
                const int col1 = col0 + 1;
                bool m00, m01, m10, m11;
                if (mode == 1) {
                    m00 = qr0 >= col0; m01 = qr0 >= col1;
                    m10 = qr1 >= col0; m11 = qr1 >= col1;
                } else if (mode == 2) {
                    const bool c0c = col0 <= 579, c1c = col1 <= 579;
                    m00 = (qr0 >= col0) || c0c; m01 = (qr0 >= col1) || c1c;
                    m10 = (qr1 >= col0) || c0c; m11 = (qr1 >= col1) || c1c;
                } else {
                    const bool pad0 = col0 < sPs[n * 8 + 2 * t];
                    const bool pad1 = col1 < sPs[n * 8 + 2 * t + 1];
                    const bool f00 = (col0 < fe0) && (col0 >= fs0);
                    const bool f01 = (col1 < fe0) && (col1 >= fs0);
                    const bool f10 = (col0 < fe1) && (col0 >= fs1);
                    const bool f11 = (col1 < fe1) && (col1 >= fs1);
                    m00 = (qr0 == col0) != ((!pad0 && (qr0 >= col0)) || f00);
                    m01 = (qr0 == col1) != ((!pad1 && (qr0 >= col1)) || f01);
                    m10 = (qr1 == col0) != ((!pad0 && (qr1 >= col0)) || f10);
                    m11 = (qr1 == col1) != ((!pad1 && (qr1 >= col1)) || f11);
                }
                if (!m00) c[n][0] = -1e30f;
                if (!m01) c[n][1] = -1e30f;
                if (!m10) c[n][2] = -1e30f;
                if (!m11) c[n][3] = -1e30f;
            }
        }

        // ---- online softmax (exp2 domain) ----
        float tm0 = -1e30f, tm1 = -1e30f;
        #pragma unroll
        for (int n = 0; n < 8; n++) {
            tm0 = fmaxf(tm0, fmaxf(c[n][0], c[n][1]));
            tm1 = fmaxf(tm1, fmaxf(c[n][2], c[n][3]));
        }
        tm0 = fmaxf(tm0, __shfl_xor_sync(0xffffffffu, tm0, 1));
        tm0 = fmaxf(tm0, __shfl_xor_sync(0xffffffffu, tm0, 2));
        tm1 = fmaxf(tm1, __shfl_xor_sync(0xffffffffu, tm1, 1));
        tm1 = fmaxf(tm1, __shfl_xor_sync(0xffffffffu, tm1, 2));
        const float mn0 = fmaxf(m0, tm0), mn1 = fmaxf(m1, tm1);
        const float al0 = ex2f(m0 - mn0), al1 = ex2f(m1 - mn1);
        float s0 = 0.f, s1 = 0.f;
        #pragma unroll
        for (int n = 0; n < 8; n++) {
            c[n][0] = ex2f(c[n][0] - mn0);
            c[n][1] = ex2f(c[n][1] - mn0);
            c[n][2] = ex2f(c[n][2] - mn1);
            c[n][3] = ex2f(c[n][3] - mn1);
            s0 += c[n][0] + c[n][1];
            s1 += c[n][2] + c[n][3];
        }
        s0 += __shfl_xor_sync(0xffffffffu, s0, 1);
        s0 += __shfl_xor_sync(0xffffffffu, s0, 2);
        s1 += __shfl_xor_sync(0xffffffffu, s1, 1);
        s1 += __shfl_xor_sync(0xffffffffu, s1, 2);
        l0 = l0 * al0 + s0;
        l1 = l1 * al1 + s1;
        m0 = mn0; m1 = mn1;
        if (!__all_sync(0xffffffffu, (al0 == 1.0f) & (al1 == 1.0f))) {
            #pragma unroll
            for (int n = 0; n < 8; n++) {
                o[n][0] *= al0; o[n][1] *= al0;
                o[n][2] *= al1; o[n][3] *= al1;
            }
        }

        // ---- O += P @ V : pack C-frags to fp16 A-frags, V^T B-frags ----
        #pragma unroll
        for (int j = 0; j < 4; j++) {
            uint32_t pa[4];
            pa[0] = packh2(c[2 * j][0],     c[2 * j][1]);       // row g,   kv 16j+2t,+1
            pa[1] = packh2(c[2 * j][2],     c[2 * j][3]);       // row g+8
            pa[2] = packh2(c[2 * j + 1][0], c[2 * j + 1][1]);   // row g,   kv 16j+2t+8,+9
            pa[3] = packh2(c[2 * j + 1][2], c[2 * j + 1][3]);   // row g+8
            #pragma unroll
            for (int n = 0; n < 8; n++) {
                const int vb = (8 * n + g) * SH + 8 * j + t;
                mma16(o[n], pa, sVs[vb], sVs[vb + 4]);
            }
        }
    }

    // ---- epilogue ----
    const float inv0 = 1.f / l0, inv1 = 1.f / l1;
    float* orow0 = gout + base + (size_t)qr0 * 64;
    float* orow1 = gout + base + (size_t)qr1 * 64;
    #pragma unroll
    for (int n = 0; n < 8; n++) {
        float2 w0 = make_float2(o[n][0] * inv0, o[n][1] * inv0);
        float2 w1 = make_float2(o[n][2] * inv1, o[n][3] * inv1);
        *(float2*)(orow0 + n * 8 + 2 * t) = w0;
        *(float2*)(orow1 + n * 8 + 2 * t) = w1;
    }
}

extern "C" void kernel_launch(void* const* d_in, const int* in_sizes, int n_in,
                              void* d_out, int out_size)
{
    const float* q   = (const float*)d_in[0];
    const float* k   = (const float*)d_in[1];
    const float* v   = (const float*)d_in[2];
    const int* pad   = (const int*)d_in[3];
    const int* fs    = (const int*)d_in[4];
    const int* fe    = (const int*)d_in[5];
    const int* bt2i  = (const int*)d_in[6];
    const int* blm   = (const int*)d_in[7];
    float* out = (float*)d_out;

    const int S = in_sizes[4];
    const int B = in_sizes[3] / S;
    const int H = (int)((long long)in_sizes[0] / ((long long)B * S * 64));

    // pre-pass: K -> fp16, V -> fp16 transposed
    dim3 pgrid(S / 64, B * H);
    prep_kernel<<<pgrid, 256>>>(k, v, S);

    const size_t smem_bytes =
        (size_t)(6 * STG_W + 128 * SH) * sizeof(uint32_t) + 208 * sizeof(int);
    cudaFuncSetAttribute(omni_attn_kernel,
                         cudaFuncAttributeMaxDynamicSharedMemorySize, (int)smem_bytes);

    dim3 grid(S / 128, B * H);
    omni_attn_kernel<<<grid, 256, smem_bytes>>>(q, pad, fs, fe, bt2i, blm, out, H, S);
}